// round 3
// baseline (speedup 1.0000x reference)
#include <cuda_runtime.h>
#include <cuda_bf16.h>
#include <cstdint>
#include <cstddef>

#define NTOK 8192
#define DIN  4096
#define DOUT 4096
#define SRNK 256

// ---------------- device scratch ----------------
__device__ __nv_bfloat16 g_Wv[2][(size_t)SRNK * DIN];   // exact sign(V_b), [S][IN]
__device__ __nv_bfloat16 g_Wu[2][(size_t)DOUT * SRNK];  // exact sign(U_b), [OUT][S]
__device__ __nv_bfloat16 g_hhi[(size_t)NTOK * 2 * SRNK];
__device__ __nv_bfloat16 g_hlo[(size_t)NTOK * 2 * SRNK];

// ---------------- helpers ----------------
__device__ __forceinline__ uint32_t smem_u32(const void* p) {
    uint32_t a;
    asm("{ .reg .u64 t; cvta.to.shared.u64 t, %1; cvt.u32.u64 %0, t; }" : "=r"(a) : "l"(p));
    return a;
}
__device__ __forceinline__ void cpa16(uint32_t dst, const void* src) {
    asm volatile("cp.async.cg.shared.global [%0], [%1], 16;" :: "r"(dst), "l"(src) : "memory");
}
#define CP_COMMIT() asm volatile("cp.async.commit_group;" ::: "memory")
#define CP_WAIT2()  asm volatile("cp.async.wait_group 2;" ::: "memory")

__device__ __forceinline__ void mma16816(float* c, const uint32_t* a, uint32_t b0, uint32_t b1) {
    asm volatile(
        "mma.sync.aligned.m16n8k16.row.col.f32.bf16.bf16.f32 "
        "{%0,%1,%2,%3}, {%4,%5,%6,%7}, {%8,%9}, {%0,%1,%2,%3};"
        : "+f"(c[0]), "+f"(c[1]), "+f"(c[2]), "+f"(c[3])
        : "r"(a[0]), "r"(a[1]), "r"(a[2]), "r"(a[3]), "r"(b0), "r"(b1));
}

__device__ __forceinline__ uint32_t bpack(__nv_bfloat16 a, __nv_bfloat16 b) {
    __nv_bfloat162 t = __halves2bfloat162(a, b);
    return *reinterpret_cast<uint32_t*>(&t);
}
// split 4 fp32 into hi/lo bf16 pairs; write pairs at (+0,+4) bytes
__device__ __forceinline__ void split_store4(char* hi, char* lo,
                                             float a0, float a1, float a2, float a3) {
    __nv_bfloat16 h0 = __float2bfloat16(a0), h1 = __float2bfloat16(a1);
    __nv_bfloat16 h2 = __float2bfloat16(a2), h3 = __float2bfloat16(a3);
    float l0 = a0 - __bfloat162float(h0), l1 = a1 - __bfloat162float(h1);
    float l2 = a2 - __bfloat162float(h2), l3 = a3 - __bfloat162float(h3);
    *reinterpret_cast<uint32_t*>(hi)     = bpack(h0, h1);
    *reinterpret_cast<uint32_t*>(hi + 4) = bpack(h2, h3);
    *reinterpret_cast<uint32_t*>(lo)     = bpack(__float2bfloat16(l0), __float2bfloat16(l1));
    *reinterpret_cast<uint32_t*>(lo + 4) = bpack(__float2bfloat16(l2), __float2bfloat16(l3));
}

// ---------------- Kw: exact sign weights ----------------
__device__ __forceinline__ __nv_bfloat16 sgn_bf(float v) {
    return __float2bfloat16(v > 0.f ? 1.f : (v < 0.f ? -1.f : 0.f));
}
__global__ void kw_kernel(const float* __restrict__ V, const float* __restrict__ VR,
                          const float* __restrict__ U, const float* __restrict__ UR) {
    const int n = SRNK * DIN;
    for (int i = blockIdx.x * blockDim.x + threadIdx.x; i < n; i += gridDim.x * blockDim.x) {
        g_Wv[0][i] = sgn_bf(V[i]);
        g_Wv[1][i] = sgn_bf(VR[i]);
        g_Wu[0][i] = sgn_bf(U[i]);
        g_Wu[1][i] = sgn_bf(UR[i]);
    }
}

// ---------------- K1 ----------------
// h_b[m, s] = sum_k (x[m,k]*v2_b[k]) * sign(V_b)[s,k], then * (v1_b*u2_b)[s],
// written as hi/lo bf16 into g_hhi/g_hlo at col br*256+s.
// CTA: Mtile=128, Ntile=256, ktile=32, 8 warps (4x2), warp tile 32x128.
#define K1_SC   0            // 256 floats (v1*u2)
#define K1_V2   1024         // 4096 floats
#define K1_X    17408        // 3 stages x 16384 (128 rows x 128B fp32)
#define K1_B    66560        // 3 stages x 20480 (256 rows x 80B)
#define K1_A    128000       // 2 bufs x 20480 (hi 10240 + lo 10240), 128 rows x 80B
#define K1_SMEM 168960

__global__ void __launch_bounds__(256, 1) k1_kernel(
    const float* __restrict__ x,
    const float* __restrict__ v2a, const float* __restrict__ v2b,
    const float* __restrict__ v1a, const float* __restrict__ u2a,
    const float* __restrict__ v1b, const float* __restrict__ u2b)
{
    extern __shared__ char sm[];
    const uint32_t smb = smem_u32(sm);
    const int tid = threadIdx.x, warp = tid >> 5, lane = tid & 31;
    const int r = lane >> 2, q = lane & 3;
    const int wm = warp >> 1, wn = warp & 1;
    const int m0 = blockIdx.x * 128;
    const int br = blockIdx.y;
    const float* v2 = br ? v2b : v2a;
    const float* v1 = br ? v1b : v1a;
    const float* u2 = br ? u2b : u2a;

    float* sc  = reinterpret_cast<float*>(sm + K1_SC);
    float* v2s = reinterpret_cast<float*>(sm + K1_V2);
    sc[tid] = v1[tid] * u2[tid];
    for (int i = tid; i < DIN; i += 256) v2s[i] = v2[i];

    // cp.async issue for ktile j
    auto issue = [&](int j) {
        if (j < DIN / 32) {
            const int s = j % 3;
            const int k0 = j * 32;
            // x: 128 rows x 128B, 2 threads/row, 4 chunks each
            {
                const int row = tid >> 1, half = tid & 1;
                uint32_t dst = smb + K1_X + s * 16384 + row * 128 + half * 64;
                const float* src = x + (size_t)(m0 + row) * DIN + k0 + half * 16;
#pragma unroll
                for (int jj = 0; jj < 4; jj++) cpa16(dst + jj * 16, src + jj * 4);
            }
            // B: 256 rows x 64B data (80B stride), 1 thread/row, 4 chunks
            {
                uint32_t dst = smb + K1_B + s * 20480 + tid * 80;
                const __nv_bfloat16* src = g_Wv[br] + (size_t)tid * DIN + k0;
#pragma unroll
                for (int jj = 0; jj < 4; jj++) cpa16(dst + jj * 16, src + jj * 8);
            }
        }
        CP_COMMIT();
    };

    issue(0); issue(1); issue(2);

    float acc[2][16][4];
#pragma unroll
    for (int a = 0; a < 2; a++)
#pragma unroll
        for (int b = 0; b < 16; b++)
#pragma unroll
            for (int c = 0; c < 4; c++) acc[a][b][c] = 0.f;

    for (int it = 0; it < DIN / 32; ++it) {
        const int s = it % 3, abuf = it & 1;
        CP_WAIT2();
        __syncthreads();

        // transform: x*v2 -> hi/lo bf16 (80B-stride tiles)
        {
            const int row = tid >> 1, half = tid & 1;
            const float4* xs = reinterpret_cast<const float4*>(sm + K1_X + s * 16384 + row * 128 + half * 64);
            const float4* vp = reinterpret_cast<const float4*>(v2s + it * 32 + half * 16);
            char* hi = sm + K1_A + abuf * 20480 + row * 80 + half * 32;
            char* lo = hi + 10240;
#pragma unroll
            for (int jj = 0; jj < 4; jj++) {
                float4 xv = xs[jj], vv = vp[jj];
                split_store4(hi + jj * 8, lo + jj * 8,
                             xv.x * vv.x, xv.y * vv.y, xv.z * vv.z, xv.w * vv.w);
            }
        }
        __syncthreads();

        // mma
        const char* A0 = sm + K1_A + abuf * 20480;
        const char* B0 = sm + K1_B + s * 20480;
#pragma unroll
        for (int s16 = 0; s16 < 2; s16++) {
            uint32_t ah[2][4], al[2][4];
#pragma unroll
            for (int mt = 0; mt < 2; mt++) {
                const char* p = A0 + (wm * 32 + mt * 16 + r) * 80 + s16 * 32 + q * 4;
                ah[mt][0] = *(const uint32_t*)(p);
                ah[mt][1] = *(const uint32_t*)(p + 640);
                ah[mt][2] = *(const uint32_t*)(p + 16);
                ah[mt][3] = *(const uint32_t*)(p + 656);
                const char* pl = p + 10240;
                al[mt][0] = *(const uint32_t*)(pl);
                al[mt][1] = *(const uint32_t*)(pl + 640);
                al[mt][2] = *(const uint32_t*)(pl + 16);
                al[mt][3] = *(const uint32_t*)(pl + 656);
            }
#pragma unroll
            for (int nt = 0; nt < 16; nt++) {
                const char* pb = B0 + (wn * 128 + nt * 8 + r) * 80 + s16 * 32 + q * 4;
                uint32_t b0 = *(const uint32_t*)(pb);
                uint32_t b1 = *(const uint32_t*)(pb + 16);
#pragma unroll
                for (int mt = 0; mt < 2; mt++) {
                    mma16816(acc[mt][nt], ah[mt], b0, b1);
                    mma16816(acc[mt][nt], al[mt], b0, b1);
                }
            }
        }
        __syncthreads();
        issue(it + 3);
    }

    // epilogue: scale by (v1*u2)[s], split hi/lo, write h
#pragma unroll
    for (int mt = 0; mt < 2; mt++) {
#pragma unroll
        for (int nt = 0; nt < 16; nt++) {
            const int row0 = m0 + wm * 32 + mt * 16 + r;
            const int col = wn * 128 + nt * 8 + 2 * q;
            const float s0 = sc[col], s1 = sc[col + 1];
            float y0 = acc[mt][nt][0] * s0, y1 = acc[mt][nt][1] * s1;
            float y2 = acc[mt][nt][2] * s0, y3 = acc[mt][nt][3] * s1;
            size_t b0i = (size_t)row0 * 512 + br * 256 + col;
            size_t b1i = b0i + 8 * 512;
            __nv_bfloat16 h0 = __float2bfloat16(y0), h1 = __float2bfloat16(y1);
            __nv_bfloat16 h2 = __float2bfloat16(y2), h3 = __float2bfloat16(y3);
            *reinterpret_cast<uint32_t*>(g_hhi + b0i) = bpack(h0, h1);
            *reinterpret_cast<uint32_t*>(g_hhi + b1i) = bpack(h2, h3);
            *reinterpret_cast<uint32_t*>(g_hlo + b0i) =
                bpack(__float2bfloat16(y0 - __bfloat162float(h0)),
                      __float2bfloat16(y1 - __bfloat162float(h1)));
            *reinterpret_cast<uint32_t*>(g_hlo + b1i) =
                bpack(__float2bfloat16(y2 - __bfloat162float(h2)),
                      __float2bfloat16(y3 - __bfloat162float(h3)));
        }
    }
}

// ---------------- K2 ----------------
// y[m,n] = sum_s h0[m,s]*sign(U)[n,s] * u1[n] + (R branch) + bias[n]
// CTA: Mtile=128, Ntile=128, K=512 (2 branches x 256), ktile=32, warp tile 32x64.
#define K2_VEC  0            // u1s[128], u1Rs[128], bs[128]
#define K2_A    1536         // 3 stages x 20480 (hi 10240 + lo 10240)
#define K2_B    62976        // 3 stages x 10240 (128 rows x 80B)
#define K2_SMEM 93696

__global__ void __launch_bounds__(256, 1) k2_kernel(
    const float* __restrict__ u1a, const float* __restrict__ u1b,
    const float* __restrict__ bias, float* __restrict__ out)
{
    extern __shared__ char sm[];
    const uint32_t smb = smem_u32(sm);
    const int tid = threadIdx.x, warp = tid >> 5, lane = tid & 31;
    const int r = lane >> 2, q = lane & 3;
    const int wm = warp >> 1, wn = warp & 1;
    const int m0 = blockIdx.x * 128;
    const int n0 = blockIdx.y * 128;

    float* u1s  = reinterpret_cast<float*>(sm + K2_VEC);
    float* u1Rs = u1s + 128;
    float* bs   = u1s + 256;
    if (tid < 128) {
        u1s[tid]  = u1a[n0 + tid];
        u1Rs[tid] = u1b[n0 + tid];
        bs[tid]   = bias[n0 + tid];
    }

    auto issue = [&](int j) {
        if (j < 16) {
            const int s = j % 3;
            const int jbr = j >> 3, jkk = j & 7;
            // A: h hi/lo, 128 rows x 64B each
            {
                const int row = tid >> 1, half = tid & 1;
                const size_t off = (size_t)(m0 + row) * 512 + jbr * 256 + jkk * 32 + half * 16;
                uint32_t dh = smb + K2_A + s * 20480 + row * 80 + half * 32;
#pragma unroll
                for (int jj = 0; jj < 2; jj++) {
                    cpa16(dh + jj * 16,         g_hhi + off + jj * 8);
                    cpa16(dh + 10240 + jj * 16, g_hlo + off + jj * 8);
                }
            }
            // B: sign(U_jbr), 128 rows x 64B
            {
                const int row = tid >> 1, half = tid & 1;
                uint32_t db = smb + K2_B + s * 10240 + row * 80 + half * 32;
                const __nv_bfloat16* src = g_Wu[jbr] + (size_t)(n0 + row) * SRNK + jkk * 32 + half * 16;
#pragma unroll
                for (int jj = 0; jj < 2; jj++) cpa16(db + jj * 16, src + jj * 8);
            }
        }
        CP_COMMIT();
    };

    issue(0); issue(1); issue(2);

    float acc[2][2][8][4];
#pragma unroll
    for (int a = 0; a < 2; a++)
#pragma unroll
        for (int b = 0; b < 2; b++)
#pragma unroll
            for (int c = 0; c < 8; c++)
#pragma unroll
                for (int d = 0; d < 4; d++) acc[a][b][c][d] = 0.f;

#pragma unroll 1
    for (int brn = 0; brn < 2; brn++) {
#pragma unroll 1
        for (int kk = 0; kk < 8; kk++) {
            const int it = brn * 8 + kk;
            const int s = it % 3;
            CP_WAIT2();
            __syncthreads();

            const char* A0 = sm + K2_A + s * 20480;
            const char* B0 = sm + K2_B + s * 10240;
#pragma unroll
            for (int s16 = 0; s16 < 2; s16++) {
                uint32_t ah[2][4], al[2][4];
#pragma unroll
                for (int mt = 0; mt < 2; mt++) {
                    const char* p = A0 + (wm * 32 + mt * 16 + r) * 80 + s16 * 32 + q * 4;
                    ah[mt][0] = *(const uint32_t*)(p);
                    ah[mt][1] = *(const uint32_t*)(p + 640);
                    ah[mt][2] = *(const uint32_t*)(p + 16);
                    ah[mt][3] = *(const uint32_t*)(p + 656);
                    const char* pl = p + 10240;
                    al[mt][0] = *(const uint32_t*)(pl);
                    al[mt][1] = *(const uint32_t*)(pl + 640);
                    al[mt][2] = *(const uint32_t*)(pl + 16);
                    al[mt][3] = *(const uint32_t*)(pl + 656);
                }
#pragma unroll
                for (int nt = 0; nt < 8; nt++) {
                    const char* pb = B0 + (wn * 64 + nt * 8 + r) * 80 + s16 * 32 + q * 4;
                    uint32_t b0 = *(const uint32_t*)(pb);
                    uint32_t b1 = *(const uint32_t*)(pb + 16);
#pragma unroll
                    for (int mt = 0; mt < 2; mt++) {
                        mma16816(acc[brn][mt][nt], ah[mt], b0, b1);
                        mma16816(acc[brn][mt][nt], al[mt], b0, b1);
                    }
                }
            }
            __syncthreads();
            issue(it + 3);
        }
    }

    // epilogue
#pragma unroll
    for (int mt = 0; mt < 2; mt++) {
#pragma unroll
        for (int nt = 0; nt < 8; nt++) {
            const int row0 = m0 + wm * 32 + mt * 16 + r;
            const int cl = wn * 64 + nt * 8 + 2 * q;
            const int col = n0 + cl;
            float2 p0, p1;
            p0.x = acc[0][mt][nt][0] * u1s[cl]     + acc[1][mt][nt][0] * u1Rs[cl]     + bs[cl];
            p0.y = acc[0][mt][nt][1] * u1s[cl + 1] + acc[1][mt][nt][1] * u1Rs[cl + 1] + bs[cl + 1];
            p1.x = acc[0][mt][nt][2] * u1s[cl]     + acc[1][mt][nt][2] * u1Rs[cl]     + bs[cl];
            p1.y = acc[0][mt][nt][3] * u1s[cl + 1] + acc[1][mt][nt][3] * u1Rs[cl + 1] + bs[cl + 1];
            *reinterpret_cast<float2*>(out + (size_t)row0 * DOUT + col) = p0;
            *reinterpret_cast<float2*>(out + (size_t)(row0 + 8) * DOUT + col) = p1;
        }
    }
}

extern "C" void kernel_launch(void* const* d_in, const int* in_sizes, int n_in,
                              void* d_out, int out_size) {
    const float* x    = (const float*)d_in[0];
    const float* V    = (const float*)d_in[1];
    const float* U    = (const float*)d_in[2];
    const float* v1   = (const float*)d_in[3];
    const float* v2   = (const float*)d_in[4];
    const float* u1   = (const float*)d_in[5];
    const float* u2   = (const float*)d_in[6];
    const float* VR   = (const float*)d_in[7];
    const float* UR   = (const float*)d_in[8];
    const float* v1R  = (const float*)d_in[9];
    const float* v2R  = (const float*)d_in[10];
    const float* u1R  = (const float*)d_in[11];
    const float* u2R  = (const float*)d_in[12];
    const float* bias = (const float*)d_in[13];
    float* out = (float*)d_out;

    static bool attr_set = false;
    if (!attr_set) {
        cudaFuncSetAttribute(k1_kernel, cudaFuncAttributeMaxDynamicSharedMemorySize, K1_SMEM);
        cudaFuncSetAttribute(k2_kernel, cudaFuncAttributeMaxDynamicSharedMemorySize, K2_SMEM);
        attr_set = true;
    }

    kw_kernel<<<512, 256>>>(V, VR, U, UR);
    k1_kernel<<<dim3(NTOK / 128, 2), 256, K1_SMEM>>>(x, v2, v2R, v1, u2, v1R, u2R);
    k2_kernel<<<dim3(NTOK / 128, DOUT / 128), 256, K2_SMEM>>>(u1, u1R, bias, out);
}

// round 5
// speedup vs baseline: 1.7526x; 1.7526x over previous
#include <cuda_runtime.h>
#include <cstdint>
#include <cstddef>

#define NTOK 8192
#define DIN  4096
#define DOUT 4096

// -------- device scratch --------
__device__ float g_Wv2[(size_t)512 * DIN];    // [s 512][k 4096]  tf32(sign(V_b)*v2_b[k])
__device__ float g_Wu2[(size_t)DOUT * 512];   // [n 4096][k 512]  tf32(sign(U_b)*u1_b[n])
__device__ float g_h[(size_t)NTOK * 512];     // tf32-rounded intermediate

// -------- helpers --------
__device__ __forceinline__ uint32_t smem_u32(const void* p) {
    uint32_t a;
    asm("{ .reg .u64 t; cvta.to.shared.u64 t, %1; cvt.u32.u64 %0, t; }" : "=r"(a) : "l"(p));
    return a;
}
__device__ __forceinline__ void cpa16(uint32_t dst, const void* src) {
    asm volatile("cp.async.cg.shared.global [%0], [%1], 16;" :: "r"(dst), "l"(src) : "memory");
}
#define CP_COMMIT() asm volatile("cp.async.commit_group;" ::: "memory")
#define CP_WAIT2()  asm volatile("cp.async.wait_group 2;" ::: "memory")

__device__ __forceinline__ float tf32r(float x) {
    uint32_t u;
    asm("cvt.rna.tf32.f32 %0, %1;" : "=r"(u) : "f"(x));
    return __uint_as_float(u);
}
__device__ __forceinline__ void mma_tf32(float* c, const uint32_t* a, uint32_t b0, uint32_t b1) {
    asm volatile(
        "mma.sync.aligned.m16n8k8.row.col.f32.tf32.tf32.f32 "
        "{%0,%1,%2,%3}, {%4,%5,%6,%7}, {%8,%9}, {%0,%1,%2,%3};"
        : "+f"(c[0]), "+f"(c[1]), "+f"(c[2]), "+f"(c[3])
        : "r"(a[0]), "r"(a[1]), "r"(a[2]), "r"(a[3]), "r"(b0), "r"(b1));
}

// -------- smem geometry (shared by k1/k2) --------
// X tile: 128 rows x 32 fp32, row stride 144B (conflict-free) -> 18432B
// B tile: 256 rows x 32 fp32, row stride 144B               -> 36864B
#define BOFF 18432
#define STG  55296
#define GSMEM (4 * STG + 1024)   // 4 stages + 256-float vector

// -------- kw: fold scales into sign weights (tf32-rounded) --------
__global__ void kw_kernel(const float* __restrict__ V,  const float* __restrict__ VR,
                          const float* __restrict__ U,  const float* __restrict__ UR,
                          const float* __restrict__ v2, const float* __restrict__ v2R,
                          const float* __restrict__ u1, const float* __restrict__ u1R) {
    int i = blockIdx.x * blockDim.x + threadIdx.x;
    if (i >= 512 * DIN) return;
    {
        int s = i >> 12, k = i & (DIN - 1);
        float w  = (s < 256) ? V[(size_t)s * DIN + k] : VR[(size_t)(s - 256) * DIN + k];
        float sv = (s < 256) ? v2[k] : v2R[k];
        float sg = (w > 0.f) ? 1.f : ((w < 0.f) ? -1.f : 0.f);
        g_Wv2[i] = tf32r(sg * sv);
    }
    {
        int n = i >> 9, kk = i & 511;
        float w  = (kk < 256) ? U[(size_t)n * 256 + kk] : UR[(size_t)n * 256 + (kk - 256)];
        float su = (kk < 256) ? u1[n] : u1R[n];
        float sg = (w > 0.f) ? 1.f : ((w < 0.f) ? -1.f : 0.f);
        g_Wu2[i] = tf32r(sg * su);
    }
}

// -------- k1: h[m, 512] = tf32r( (x @ Wv2^T) * (v1*u2) ) --------
__global__ void __launch_bounds__(256, 1) k1_kernel(
    const float* __restrict__ x,
    const float* __restrict__ v1a, const float* __restrict__ u2a,
    const float* __restrict__ v1b, const float* __restrict__ u2b)
{
    extern __shared__ char sm[];
    const uint32_t smb = smem_u32(sm);
    const int tid = threadIdx.x, warp = tid >> 5, lane = tid & 31;
    const int r = lane >> 2, q = lane & 3;
    const int wm = warp >> 1, wn = warp & 1;
    const int m0 = blockIdx.x * 128;
    const int by = blockIdx.y;                 // branch half, n0 = by*256

    float* sc = reinterpret_cast<float*>(sm + 4 * STG);
    {
        const float* v1 = by ? v1b : v1a;
        const float* u2 = by ? u2b : u2a;
        sc[tid] = v1[tid] * u2[tid];
    }
    const int xrow = tid >> 1, xhalf = tid & 1;

    auto issue = [&](int j) {
        if (j < 128) {
            const int s4 = j & 3, k0 = j * 32;
            uint32_t xd = smb + s4 * STG + xrow * 144 + xhalf * 64;
            const float* xs = x + (size_t)(m0 + xrow) * DIN + k0 + xhalf * 16;
#pragma unroll
            for (int c = 0; c < 4; c++) cpa16(xd + c * 16, xs + c * 4);
            uint32_t bd = smb + s4 * STG + BOFF + tid * 144;
            const float* bsrc = g_Wv2 + (size_t)(by * 256 + tid) * DIN + k0;
#pragma unroll
            for (int c = 0; c < 8; c++) cpa16(bd + c * 16, bsrc + c * 4);
        }
        CP_COMMIT();
    };
    issue(0); issue(1); issue(2);

    float acc[2][16][4];
#pragma unroll
    for (int a = 0; a < 2; a++)
#pragma unroll
        for (int b = 0; b < 16; b++)
#pragma unroll
            for (int c = 0; c < 4; c++) acc[a][b][c] = 0.f;

    for (int it = 0; it < 128; ++it) {
        CP_WAIT2();
        __syncthreads();
        issue(it + 3);
        const char* Xb = sm + (it & 3) * STG;
        const char* Bb = Xb + BOFF;
#pragma unroll
        for (int s8 = 0; s8 < 4; s8++) {
            uint32_t a[2][4];
#pragma unroll
            for (int mt = 0; mt < 2; mt++) {
                const char* p = Xb + (wm * 32 + mt * 16 + r) * 144 + s8 * 32 + q * 4;
                a[mt][0] = *(const uint32_t*)(p);
                a[mt][1] = *(const uint32_t*)(p + 1152);
                a[mt][2] = *(const uint32_t*)(p + 16);
                a[mt][3] = *(const uint32_t*)(p + 1168);
#pragma unroll
                for (int e = 0; e < 4; e++) {
                    uint32_t o;
                    asm("cvt.rna.tf32.f32 %0, %1;" : "=r"(o) : "f"(__uint_as_float(a[mt][e])));
                    a[mt][e] = o;
                }
            }
#pragma unroll
            for (int nt = 0; nt < 16; nt++) {
                const char* pb = Bb + (wn * 128 + nt * 8 + r) * 144 + s8 * 32 + q * 4;
                uint32_t b0 = *(const uint32_t*)(pb);
                uint32_t b1 = *(const uint32_t*)(pb + 16);
                mma_tf32(acc[0][nt], a[0], b0, b1);
                mma_tf32(acc[1][nt], a[1], b0, b1);
            }
        }
    }

    // epilogue: scale by (v1*u2), round to tf32, store h
#pragma unroll
    for (int mt = 0; mt < 2; mt++) {
#pragma unroll
        for (int nt = 0; nt < 16; nt++) {
            const int row = m0 + wm * 32 + mt * 16 + r;
            const int cl = wn * 128 + nt * 8 + 2 * q;
            const int col = by * 256 + cl;
            const float s0 = sc[cl], s1 = sc[cl + 1];
            float2 p0, p1;
            p0.x = tf32r(acc[mt][nt][0] * s0);
            p0.y = tf32r(acc[mt][nt][1] * s1);
            p1.x = tf32r(acc[mt][nt][2] * s0);
            p1.y = tf32r(acc[mt][nt][3] * s1);
            *reinterpret_cast<float2*>(g_h + (size_t)row * 512 + col) = p0;
            *reinterpret_cast<float2*>(g_h + (size_t)(row + 8) * 512 + col) = p1;
        }
    }
}

// -------- k2: y[m, n] = h @ Wu2^T + bias --------
__global__ void __launch_bounds__(256, 1) k2_kernel(
    const float* __restrict__ bias, float* __restrict__ out)
{
    extern __shared__ char sm[];
    const uint32_t smb = smem_u32(sm);
    const int tid = threadIdx.x, warp = tid >> 5, lane = tid & 31;
    const int r = lane >> 2, q = lane & 3;
    const int wm = warp >> 1, wn = warp & 1;
    const int m0 = blockIdx.x * 128;
    const int n0 = blockIdx.y * 256;

    float* bs = reinterpret_cast<float*>(sm + 4 * STG);
    bs[tid] = bias[n0 + tid];
    const int xrow = tid >> 1, xhalf = tid & 1;

    auto issue = [&](int j) {
        if (j < 16) {
            const int s4 = j & 3, k0 = j * 32;
            uint32_t xd = smb + s4 * STG + xrow * 144 + xhalf * 64;
            const float* xs = g_h + (size_t)(m0 + xrow) * 512 + k0 + xhalf * 16;
#pragma unroll
            for (int c = 0; c < 4; c++) cpa16(xd + c * 16, xs + c * 4);
            uint32_t bd = smb + s4 * STG + BOFF + tid * 144;
            const float* bsrc = g_Wu2 + (size_t)(n0 + tid) * 512 + k0;
#pragma unroll
            for (int c = 0; c < 8; c++) cpa16(bd + c * 16, bsrc + c * 4);
        }
        CP_COMMIT();
    };
    issue(0); issue(1); issue(2);

    float acc[2][16][4];
#pragma unroll
    for (int a = 0; a < 2; a++)
#pragma unroll
        for (int b = 0; b < 16; b++)
#pragma unroll
            for (int c = 0; c < 4; c++) acc[a][b][c] = 0.f;

    for (int it = 0; it < 16; ++it) {
        CP_WAIT2();
        __syncthreads();
        issue(it + 3);
        const char* Xb = sm + (it & 3) * STG;
        const char* Bb = Xb + BOFF;
#pragma unroll
        for (int s8 = 0; s8 < 4; s8++) {
            uint32_t a[2][4];
#pragma unroll
            for (int mt = 0; mt < 2; mt++) {
                const char* p = Xb + (wm * 32 + mt * 16 + r) * 144 + s8 * 32 + q * 4;
                a[mt][0] = *(const uint32_t*)(p);
                a[mt][1] = *(const uint32_t*)(p + 1152);
                a[mt][2] = *(const uint32_t*)(p + 16);
                a[mt][3] = *(const uint32_t*)(p + 1168);
            }
#pragma unroll
            for (int nt = 0; nt < 16; nt++) {
                const char* pb = Bb + (wn * 128 + nt * 8 + r) * 144 + s8 * 32 + q * 4;
                uint32_t b0 = *(const uint32_t*)(pb);
                uint32_t b1 = *(const uint32_t*)(pb + 16);
                mma_tf32(acc[0][nt], a[0], b0, b1);
                mma_tf32(acc[1][nt], a[1], b0, b1);
            }
        }
    }

    // epilogue: + bias (u1 folded into Wu2)
#pragma unroll
    for (int mt = 0; mt < 2; mt++) {
#pragma unroll
        for (int nt = 0; nt < 16; nt++) {
            const int row = m0 + wm * 32 + mt * 16 + r;
            const int cl = wn * 128 + nt * 8 + 2 * q;
            const int col = n0 + cl;
            float2 p0, p1;
            p0.x = acc[mt][nt][0] + bs[cl];
            p0.y = acc[mt][nt][1] + bs[cl + 1];
            p1.x = acc[mt][nt][2] + bs[cl];
            p1.y = acc[mt][nt][3] + bs[cl + 1];
            *reinterpret_cast<float2*>(out + (size_t)row * DOUT + col) = p0;
            *reinterpret_cast<float2*>(out + (size_t)(row + 8) * DOUT + col) = p1;
        }
    }
}

extern "C" void kernel_launch(void* const* d_in, const int* in_sizes, int n_in,
                              void* d_out, int out_size) {
    const float* x    = (const float*)d_in[0];
    const float* V    = (const float*)d_in[1];
    const float* U    = (const float*)d_in[2];
    const float* v1   = (const float*)d_in[3];
    const float* v2   = (const float*)d_in[4];
    const float* u1   = (const float*)d_in[5];
    const float* u2   = (const float*)d_in[6];
    const float* VR   = (const float*)d_in[7];
    const float* UR   = (const float*)d_in[8];
    const float* v1R  = (const float*)d_in[9];
    const float* v2R  = (const float*)d_in[10];
    const float* u1R  = (const float*)d_in[11];
    const float* u2R  = (const float*)d_in[12];
    const float* bias = (const float*)d_in[13];
    float* out = (float*)d_out;

    static bool attr_set = false;
    if (!attr_set) {
        cudaFuncSetAttribute(k1_kernel, cudaFuncAttributeMaxDynamicSharedMemorySize, GSMEM);
        cudaFuncSetAttribute(k2_kernel, cudaFuncAttributeMaxDynamicSharedMemorySize, GSMEM);
        attr_set = true;
    }

    kw_kernel<<<8192, 256>>>(V, VR, U, UR, v2, v2R, u1, u1R);
    k1_kernel<<<dim3(NTOK / 128, 2), 256, GSMEM>>>(x, v1, u2, v1R, u2R);
    k2_kernel<<<dim3(NTOK / 128, DOUT / 256), 256, GSMEM>>>(bias, out);
}

// round 6
// speedup vs baseline: 3.0425x; 1.7360x over previous
#include <cuda_runtime.h>
#include <cuda_fp16.h>
#include <cstdint>
#include <cstddef>

#define NTOK 8192
#define DIN  4096
#define DOUT 4096

// -------- device scratch --------
__device__ __half g_xh[(size_t)NTOK * DIN];    // fp16(x)
__device__ __half g_Wv2[(size_t)512 * DIN];    // [s 512][k 4096]  fp16(sign(V_b)*v2_b[k])
__device__ __half g_Wu2[(size_t)DOUT * 512];   // [n 4096][k 512]  fp16(sign(U_b)*u1_b[n])
__device__ __half g_h[(size_t)NTOK * 512];     // fp16 intermediate (v1*u2 applied)

// -------- helpers --------
__device__ __forceinline__ uint32_t smem_u32(const void* p) {
    uint32_t a;
    asm("{ .reg .u64 t; cvta.to.shared.u64 t, %1; cvt.u32.u64 %0, t; }" : "=r"(a) : "l"(p));
    return a;
}
__device__ __forceinline__ void cpa16(uint32_t dst, const void* src) {
    asm volatile("cp.async.cg.shared.global [%0], [%1], 16;" :: "r"(dst), "l"(src) : "memory");
}
#define CP_COMMIT() asm volatile("cp.async.commit_group;" ::: "memory")
#define CP_WAIT2()  asm volatile("cp.async.wait_group 2;" ::: "memory")

__device__ __forceinline__ void mma_fp16(float* c, const uint32_t* a, uint32_t b0, uint32_t b1) {
    asm volatile(
        "mma.sync.aligned.m16n8k16.row.col.f32.f16.f16.f32 "
        "{%0,%1,%2,%3}, {%4,%5,%6,%7}, {%8,%9}, {%0,%1,%2,%3};"
        : "+f"(c[0]), "+f"(c[1]), "+f"(c[2]), "+f"(c[3])
        : "r"(a[0]), "r"(a[1]), "r"(a[2]), "r"(a[3]), "r"(b0), "r"(b1));
}

// -------- smem geometry (shared by k1/k2) --------
// A tile: 128 rows x 64 fp16 (128B), row stride 144B -> 18432B
// B tile: 256 rows x 64 fp16 (128B), row stride 144B -> 36864B
#define BOFF 18432
#define STG  55296
#define GSMEM (4 * STG + 1024)

// -------- kc: x -> fp16 --------
__global__ void kc_kernel(const float* __restrict__ x) {
    size_t i = ((size_t)blockIdx.x * blockDim.x + threadIdx.x) * 8;
    if (i >= (size_t)NTOK * DIN) return;
    float4 a = *reinterpret_cast<const float4*>(x + i);
    float4 b = *reinterpret_cast<const float4*>(x + i + 4);
    uint2 o;
    __half2 h0 = __floats2half2_rn(a.x, a.y);
    __half2 h1 = __floats2half2_rn(a.z, a.w);
    __half2 h2 = __floats2half2_rn(b.x, b.y);
    __half2 h3 = __floats2half2_rn(b.z, b.w);
    o.x = (*reinterpret_cast<uint32_t*>(&h0)) ;
    o.y = (*reinterpret_cast<uint32_t*>(&h1));
    uint2 o2;
    o2.x = (*reinterpret_cast<uint32_t*>(&h2));
    o2.y = (*reinterpret_cast<uint32_t*>(&h3));
    *reinterpret_cast<uint2*>(g_xh + i) = o;
    *reinterpret_cast<uint2*>(g_xh + i + 4) = o2;
}

// -------- kw: fold scales into sign weights (fp16) --------
__global__ void kw_kernel(const float* __restrict__ V,  const float* __restrict__ VR,
                          const float* __restrict__ U,  const float* __restrict__ UR,
                          const float* __restrict__ v2, const float* __restrict__ v2R,
                          const float* __restrict__ u1, const float* __restrict__ u1R) {
    int i = blockIdx.x * blockDim.x + threadIdx.x;
    if (i >= 512 * DIN) return;
    {
        int s = i >> 12, k = i & (DIN - 1);
        float w  = (s < 256) ? V[(size_t)s * DIN + k] : VR[(size_t)(s - 256) * DIN + k];
        float sv = (s < 256) ? v2[k] : v2R[k];
        float sg = (w > 0.f) ? 1.f : ((w < 0.f) ? -1.f : 0.f);
        g_Wv2[i] = __float2half(sg * sv);
    }
    {
        int n = i >> 9, kk = i & 511;
        float w  = (kk < 256) ? U[(size_t)n * 256 + kk] : UR[(size_t)n * 256 + (kk - 256)];
        float su = (kk < 256) ? u1[n] : u1R[n];
        float sg = (w > 0.f) ? 1.f : ((w < 0.f) ? -1.f : 0.f);
        g_Wu2[i] = __float2half(sg * su);
    }
}

// -------- k1: h[m, 512] = fp16( (x @ Wv2^T) * (v1*u2) ) --------
__global__ void __launch_bounds__(256, 1) k1_kernel(
    const float* __restrict__ v1a, const float* __restrict__ u2a,
    const float* __restrict__ v1b, const float* __restrict__ u2b)
{
    extern __shared__ char sm[];
    const uint32_t smb = smem_u32(sm);
    const int tid = threadIdx.x, warp = tid >> 5, lane = tid & 31;
    const int r = lane >> 2, q = lane & 3;
    const int wm = warp >> 1, wn = warp & 1;
    const int m0 = blockIdx.x * 128;
    const int by = blockIdx.y;                 // branch half, n0 = by*256

    float* sc = reinterpret_cast<float*>(sm + 4 * STG);
    {
        const float* v1 = by ? v1b : v1a;
        const float* u2 = by ? u2b : u2a;
        sc[tid] = v1[tid] * u2[tid];
    }
    const int xrow = tid >> 1, xhalf = tid & 1;

    auto issue = [&](int j) {
        if (j < 64) {
            const int s4 = j & 3, k0 = j * 64;
            uint32_t xd = smb + s4 * STG + xrow * 144 + xhalf * 64;
            const __half* xs = g_xh + (size_t)(m0 + xrow) * DIN + k0 + xhalf * 32;
#pragma unroll
            for (int c = 0; c < 4; c++) cpa16(xd + c * 16, xs + c * 8);
            uint32_t bd = smb + s4 * STG + BOFF + tid * 144;
            const __half* bsrc = g_Wv2 + (size_t)(by * 256 + tid) * DIN + k0;
#pragma unroll
            for (int c = 0; c < 8; c++) cpa16(bd + c * 16, bsrc + c * 8);
        }
        CP_COMMIT();
    };
    issue(0); issue(1); issue(2);

    float acc[2][16][4];
#pragma unroll
    for (int a = 0; a < 2; a++)
#pragma unroll
        for (int b = 0; b < 16; b++)
#pragma unroll
            for (int c = 0; c < 4; c++) acc[a][b][c] = 0.f;

    for (int it = 0; it < 64; ++it) {
        CP_WAIT2();
        __syncthreads();
        issue(it + 3);
        const char* Xb = sm + (it & 3) * STG;
        const char* Bb = Xb + BOFF;
#pragma unroll
        for (int s16 = 0; s16 < 4; s16++) {
            uint32_t a[2][4];
#pragma unroll
            for (int mt = 0; mt < 2; mt++) {
                const char* p = Xb + (wm * 32 + mt * 16 + r) * 144 + s16 * 32 + q * 4;
                a[mt][0] = *(const uint32_t*)(p);
                a[mt][1] = *(const uint32_t*)(p + 1152);
                a[mt][2] = *(const uint32_t*)(p + 16);
                a[mt][3] = *(const uint32_t*)(p + 1168);
            }
#pragma unroll
            for (int nt = 0; nt < 16; nt++) {
                const char* pb = Bb + (wn * 128 + nt * 8 + r) * 144 + s16 * 32 + q * 4;
                uint32_t b0 = *(const uint32_t*)(pb);
                uint32_t b1 = *(const uint32_t*)(pb + 16);
                mma_fp16(acc[0][nt], a[0], b0, b1);
                mma_fp16(acc[1][nt], a[1], b0, b1);
            }
        }
    }

    // epilogue: scale by (v1*u2), convert fp16, store h
#pragma unroll
    for (int mt = 0; mt < 2; mt++) {
#pragma unroll
        for (int nt = 0; nt < 16; nt++) {
            const int row = m0 + wm * 32 + mt * 16 + r;
            const int cl = wn * 128 + nt * 8 + 2 * q;
            const int col = by * 256 + cl;
            const float s0 = sc[cl], s1 = sc[cl + 1];
            __half2 p0 = __floats2half2_rn(acc[mt][nt][0] * s0, acc[mt][nt][1] * s1);
            __half2 p1 = __floats2half2_rn(acc[mt][nt][2] * s0, acc[mt][nt][3] * s1);
            *reinterpret_cast<uint32_t*>(g_h + (size_t)row * 512 + col) =
                *reinterpret_cast<uint32_t*>(&p0);
            *reinterpret_cast<uint32_t*>(g_h + (size_t)(row + 8) * 512 + col) =
                *reinterpret_cast<uint32_t*>(&p1);
        }
    }
}

// -------- k2: y[m, n] = h @ Wu2^T + bias --------
__global__ void __launch_bounds__(256, 1) k2_kernel(
    const float* __restrict__ bias, float* __restrict__ out)
{
    extern __shared__ char sm[];
    const uint32_t smb = smem_u32(sm);
    const int tid = threadIdx.x, warp = tid >> 5, lane = tid & 31;
    const int r = lane >> 2, q = lane & 3;
    const int wm = warp >> 1, wn = warp & 1;
    const int m0 = blockIdx.x * 128;
    const int n0 = blockIdx.y * 256;

    float* bs = reinterpret_cast<float*>(sm + 4 * STG);
    bs[tid] = bias[n0 + tid];
    const int xrow = tid >> 1, xhalf = tid & 1;

    auto issue = [&](int j) {
        if (j < 8) {
            const int s4 = j & 3, k0 = j * 64;
            uint32_t xd = smb + s4 * STG + xrow * 144 + xhalf * 64;
            const __half* xs = g_h + (size_t)(m0 + xrow) * 512 + k0 + xhalf * 32;
#pragma unroll
            for (int c = 0; c < 4; c++) cpa16(xd + c * 16, xs + c * 8);
            uint32_t bd = smb + s4 * STG + BOFF + tid * 144;
            const __half* bsrc = g_Wu2 + (size_t)(n0 + tid) * 512 + k0;
#pragma unroll
            for (int c = 0; c < 8; c++) cpa16(bd + c * 16, bsrc + c * 8);
        }
        CP_COMMIT();
    };
    issue(0); issue(1); issue(2);

    float acc[2][16][4];
#pragma unroll
    for (int a = 0; a < 2; a++)
#pragma unroll
        for (int b = 0; b < 16; b++)
#pragma unroll
            for (int c = 0; c < 4; c++) acc[a][b][c] = 0.f;

    for (int it = 0; it < 8; ++it) {
        CP_WAIT2();
        __syncthreads();
        issue(it + 3);
        const char* Xb = sm + (it & 3) * STG;
        const char* Bb = Xb + BOFF;
#pragma unroll
        for (int s16 = 0; s16 < 4; s16++) {
            uint32_t a[2][4];
#pragma unroll
            for (int mt = 0; mt < 2; mt++) {
                const char* p = Xb + (wm * 32 + mt * 16 + r) * 144 + s16 * 32 + q * 4;
                a[mt][0] = *(const uint32_t*)(p);
                a[mt][1] = *(const uint32_t*)(p + 1152);
                a[mt][2] = *(const uint32_t*)(p + 16);
                a[mt][3] = *(const uint32_t*)(p + 1168);
            }
#pragma unroll
            for (int nt = 0; nt < 16; nt++) {
                const char* pb = Bb + (wn * 128 + nt * 8 + r) * 144 + s16 * 32 + q * 4;
                uint32_t b0 = *(const uint32_t*)(pb);
                uint32_t b1 = *(const uint32_t*)(pb + 16);
                mma_fp16(acc[0][nt], a[0], b0, b1);
                mma_fp16(acc[1][nt], a[1], b0, b1);
            }
        }
    }

    // epilogue: + bias (u1 folded into Wu2)
#pragma unroll
    for (int mt = 0; mt < 2; mt++) {
#pragma unroll
        for (int nt = 0; nt < 16; nt++) {
            const int row = m0 + wm * 32 + mt * 16 + r;
            const int cl = wn * 128 + nt * 8 + 2 * q;
            const int col = n0 + cl;
            float2 p0, p1;
            p0.x = acc[mt][nt][0] + bs[cl];
            p0.y = acc[mt][nt][1] + bs[cl + 1];
            p1.x = acc[mt][nt][2] + bs[cl];
            p1.y = acc[mt][nt][3] + bs[cl + 1];
            *reinterpret_cast<float2*>(out + (size_t)row * DOUT + col) = p0;
            *reinterpret_cast<float2*>(out + (size_t)(row + 8) * DOUT + col) = p1;
        }
    }
}

extern "C" void kernel_launch(void* const* d_in, const int* in_sizes, int n_in,
                              void* d_out, int out_size) {
    const float* x    = (const float*)d_in[0];
    const float* V    = (const float*)d_in[1];
    const float* U    = (const float*)d_in[2];
    const float* v1   = (const float*)d_in[3];
    const float* v2   = (const float*)d_in[4];
    const float* u1   = (const float*)d_in[5];
    const float* u2   = (const float*)d_in[6];
    const float* VR   = (const float*)d_in[7];
    const float* UR   = (const float*)d_in[8];
    const float* v1R  = (const float*)d_in[9];
    const float* v2R  = (const float*)d_in[10];
    const float* u1R  = (const float*)d_in[11];
    const float* u2R  = (const float*)d_in[12];
    const float* bias = (const float*)d_in[13];
    float* out = (float*)d_out;

    static bool attr_set = false;
    if (!attr_set) {
        cudaFuncSetAttribute(k1_kernel, cudaFuncAttributeMaxDynamicSharedMemorySize, GSMEM);
        cudaFuncSetAttribute(k2_kernel, cudaFuncAttributeMaxDynamicSharedMemorySize, GSMEM);
        attr_set = true;
    }

    kc_kernel<<<(NTOK * (size_t)DIN) / (256 * 8), 256>>>(x);
    kw_kernel<<<8192, 256>>>(V, VR, U, UR, v2, v2R, u1, u1R);
    k1_kernel<<<dim3(NTOK / 128, 2), 256, GSMEM>>>(v1, u2, v1R, u2R);
    k2_kernel<<<dim3(NTOK / 128, DOUT / 256), 256, GSMEM>>>(bias, out);
}

// round 8
// speedup vs baseline: 3.2909x; 1.0816x over previous
#include <cuda_runtime.h>
#include <cuda_fp16.h>
#include <cstdint>
#include <cstddef>

#define NTOK 8192
#define DIN  4096
#define DOUT 4096

// -------- device scratch --------
__device__ __half g_xh[(size_t)NTOK * DIN];    // fp16(x)
__device__ __half g_Wv2[(size_t)512 * DIN];    // [s 512][k 4096]  fp16(sign(V_b)*v2_b[k])
__device__ __half g_Wu2[(size_t)DOUT * 512];   // [n 4096][k 512]  fp16(sign(U_b)*u1_b[n])
__device__ __half g_h[(size_t)NTOK * 512];     // fp16 intermediate (v1*u2 applied)

// -------- helpers --------
__device__ __forceinline__ uint32_t smem_u32(const void* p) {
    uint32_t a;
    asm("{ .reg .u64 t; cvta.to.shared.u64 t, %1; cvt.u32.u64 %0, t; }" : "=r"(a) : "l"(p));
    return a;
}
__device__ __forceinline__ void cpa16(uint32_t dst, const void* src) {
    asm volatile("cp.async.cg.shared.global [%0], [%1], 16;" :: "r"(dst), "l"(src) : "memory");
}
#define CP_COMMIT() asm volatile("cp.async.commit_group;" ::: "memory")
#define CP_WAIT2()  asm volatile("cp.async.wait_group 2;" ::: "memory")

__device__ __forceinline__ void mma_fp16(float* c, const uint32_t* a, uint32_t b0, uint32_t b1) {
    asm volatile(
        "mma.sync.aligned.m16n8k16.row.col.f32.f16.f16.f32 "
        "{%0,%1,%2,%3}, {%4,%5,%6,%7}, {%8,%9}, {%0,%1,%2,%3};"
        : "+f"(c[0]), "+f"(c[1]), "+f"(c[2]), "+f"(c[3])
        : "r"(a[0]), "r"(a[1]), "r"(a[2]), "r"(a[3]), "r"(b0), "r"(b1));
}

// -------- smem geometry --------
// A tile: 128 rows x 32 fp16 (64B data), row stride 80B -> 10240B
// B tile: 128 rows x 32 fp16 (64B data), row stride 80B -> 10240B
// stage = 20480B, 4 stages = 81920B -> 2 CTAs/SM
#define BOFF 10240
#define STG  20480
#define GSMEM (4 * STG + 1024)

// -------- kc: x -> fp16 --------
__global__ void kc_kernel(const float* __restrict__ x) {
    size_t i = ((size_t)blockIdx.x * blockDim.x + threadIdx.x) * 8;
    if (i >= (size_t)NTOK * DIN) return;
    float4 a = *reinterpret_cast<const float4*>(x + i);
    float4 b = *reinterpret_cast<const float4*>(x + i + 4);
    __half2 h0 = __floats2half2_rn(a.x, a.y);
    __half2 h1 = __floats2half2_rn(a.z, a.w);
    __half2 h2 = __floats2half2_rn(b.x, b.y);
    __half2 h3 = __floats2half2_rn(b.z, b.w);
    uint2 o, o2;
    o.x  = *reinterpret_cast<uint32_t*>(&h0);
    o.y  = *reinterpret_cast<uint32_t*>(&h1);
    o2.x = *reinterpret_cast<uint32_t*>(&h2);
    o2.y = *reinterpret_cast<uint32_t*>(&h3);
    *reinterpret_cast<uint2*>(g_xh + i) = o;
    *reinterpret_cast<uint2*>(g_xh + i + 4) = o2;
}

// -------- kw: fold scales into sign weights (fp16) --------
__global__ void kw_kernel(const float* __restrict__ V,  const float* __restrict__ VR,
                          const float* __restrict__ U,  const float* __restrict__ UR,
                          const float* __restrict__ v2, const float* __restrict__ v2R,
                          const float* __restrict__ u1, const float* __restrict__ u1R) {
    int i = blockIdx.x * blockDim.x + threadIdx.x;
    if (i >= 512 * DIN) return;
    {
        int s = i >> 12, k = i & (DIN - 1);
        float w  = (s < 256) ? V[(size_t)s * DIN + k] : VR[(size_t)(s - 256) * DIN + k];
        float sv = (s < 256) ? v2[k] : v2R[k];
        float sg = (w > 0.f) ? 1.f : ((w < 0.f) ? -1.f : 0.f);
        g_Wv2[i] = __float2half(sg * sv);
    }
    {
        int n = i >> 9, kk = i & 511;
        float w  = (kk < 256) ? U[(size_t)n * 256 + kk] : UR[(size_t)n * 256 + (kk - 256)];
        float su = (kk < 256) ? u1[n] : u1R[n];
        float sg = (w > 0.f) ? 1.f : ((w < 0.f) ? -1.f : 0.f);
        g_Wu2[i] = __float2half(sg * su);
    }
}

// -------- k1: h[m, 512] = fp16( (x @ Wv2^T) * (v1*u2) ) --------
// grid (64, 4): y = branch*2 + nhalf. CTA tile 128x128, ktile 32, 64 iters.
__global__ void __launch_bounds__(256, 2) k1_kernel(
    const float* __restrict__ v1a, const float* __restrict__ u2a,
    const float* __restrict__ v1b, const float* __restrict__ u2b)
{
    extern __shared__ char sm[];
    const uint32_t smb = smem_u32(sm);
    const int tid = threadIdx.x, warp = tid >> 5, lane = tid & 31;
    const int r = lane >> 2, q = lane & 3;
    const int wm = warp >> 1, wn = warp & 1;
    const int m0 = blockIdx.x * 128;
    const int by = blockIdx.y;
    const int br = by >> 1, nb = (by & 1) * 128;

    float* sc = reinterpret_cast<float*>(sm + 4 * STG);
    if (tid < 128) {
        const float* v1 = br ? v1b : v1a;
        const float* u2 = br ? u2b : u2a;
        sc[tid] = v1[nb + tid] * u2[nb + tid];
    }
    const int row = tid >> 1, half = tid & 1;

    auto issue = [&](int j) {
        if (j < 128) {
            const int s4 = j & 3, k0 = j * 32;
            uint32_t xd = smb + s4 * STG + row * 80 + half * 32;
            const __half* xs = g_xh + (size_t)(m0 + row) * DIN + k0 + half * 16;
            cpa16(xd, xs);
            cpa16(xd + 16, xs + 8);
            uint32_t bd = smb + s4 * STG + BOFF + row * 80 + half * 32;
            const __half* bsrc = g_Wv2 + (size_t)(br * 256 + nb + row) * DIN + k0 + half * 16;
            cpa16(bd, bsrc);
            cpa16(bd + 16, bsrc + 8);
        }
        CP_COMMIT();
    };
    issue(0); issue(1); issue(2);

    float acc[2][8][4];
#pragma unroll
    for (int a = 0; a < 2; a++)
#pragma unroll
        for (int b = 0; b < 8; b++)
#pragma unroll
            for (int c = 0; c < 4; c++) acc[a][b][c] = 0.f;

    for (int it = 0; it < 128; ++it) {
        CP_WAIT2();
        __syncthreads();
        issue(it + 3);
        const char* Xb = sm + (it & 3) * STG;
        const char* Bb = Xb + BOFF;
#pragma unroll
        for (int s16 = 0; s16 < 2; s16++) {
            uint32_t a[2][4];
#pragma unroll
            for (int mt = 0; mt < 2; mt++) {
                const char* p = Xb + (wm * 32 + mt * 16 + r) * 80 + s16 * 32 + q * 4;
                a[mt][0] = *(const uint32_t*)(p);
                a[mt][1] = *(const uint32_t*)(p + 640);
                a[mt][2] = *(const uint32_t*)(p + 16);
                a[mt][3] = *(const uint32_t*)(p + 656);
            }
#pragma unroll
            for (int nt = 0; nt < 8; nt++) {
                const char* pb = Bb + (wn * 64 + nt * 8 + r) * 80 + s16 * 32 + q * 4;
                uint32_t b0 = *(const uint32_t*)(pb);
                uint32_t b1 = *(const uint32_t*)(pb + 16);
                mma_fp16(acc[0][nt], a[0], b0, b1);
                mma_fp16(acc[1][nt], a[1], b0, b1);
            }
        }
    }

    // epilogue: scale by (v1*u2), convert fp16, store h
#pragma unroll
    for (int mt = 0; mt < 2; mt++) {
#pragma unroll
        for (int nt = 0; nt < 8; nt++) {
            const int rw = m0 + wm * 32 + mt * 16 + r;
            const int cl = wn * 64 + nt * 8 + 2 * q;
            const int col = br * 256 + nb + cl;
            const float s0 = sc[cl], s1 = sc[cl + 1];
            __half2 p0 = __floats2half2_rn(acc[mt][nt][0] * s0, acc[mt][nt][1] * s1);
            __half2 p1 = __floats2half2_rn(acc[mt][nt][2] * s0, acc[mt][nt][3] * s1);
            *reinterpret_cast<uint32_t*>(g_h + (size_t)rw * 512 + col) =
                *reinterpret_cast<uint32_t*>(&p0);
            *reinterpret_cast<uint32_t*>(g_h + (size_t)(rw + 8) * 512 + col) =
                *reinterpret_cast<uint32_t*>(&p1);
        }
    }
}

// -------- k2: y[m, n] = h @ Wu2^T + bias --------
// grid (64, 32). CTA tile 128x128, K=512, ktile 32, 16 iters.
__global__ void __launch_bounds__(256, 2) k2_kernel(
    const float* __restrict__ bias, float* __restrict__ out)
{
    extern __shared__ char sm[];
    const uint32_t smb = smem_u32(sm);
    const int tid = threadIdx.x, warp = tid >> 5, lane = tid & 31;
    const int r = lane >> 2, q = lane & 3;
    const int wm = warp >> 1, wn = warp & 1;
    const int m0 = blockIdx.x * 128;
    const int n0 = blockIdx.y * 128;

    float* bs = reinterpret_cast<float*>(sm + 4 * STG);
    if (tid < 128) bs[tid] = bias[n0 + tid];
    const int row = tid >> 1, half = tid & 1;

    auto issue = [&](int j) {
        if (j < 16) {
            const int s4 = j & 3, k0 = j * 32;
            uint32_t xd = smb + s4 * STG + row * 80 + half * 32;
            const __half* xs = g_h + (size_t)(m0 + row) * 512 + k0 + half * 16;
            cpa16(xd, xs);
            cpa16(xd + 16, xs + 8);
            uint32_t bd = smb + s4 * STG + BOFF + row * 80 + half * 32;
            const __half* bsrc = g_Wu2 + (size_t)(n0 + row) * 512 + k0 + half * 16;
            cpa16(bd, bsrc);
            cpa16(bd + 16, bsrc + 8);
        }
        CP_COMMIT();
    };
    issue(0); issue(1); issue(2);

    float acc[2][8][4];
#pragma unroll
    for (int a = 0; a < 2; a++)
#pragma unroll
        for (int b = 0; b < 8; b++)
#pragma unroll
            for (int c = 0; c < 4; c++) acc[a][b][c] = 0.f;

    for (int it = 0; it < 16; ++it) {
        CP_WAIT2();
        __syncthreads();
        issue(it + 3);
        const char* Xb = sm + (it & 3) * STG;
        const char* Bb = Xb + BOFF;
#pragma unroll
        for (int s16 = 0; s16 < 2; s16++) {
            uint32_t a[2][4];
#pragma unroll
            for (int mt = 0; mt < 2; mt++) {
                const char* p = Xb + (wm * 32 + mt * 16 + r) * 80 + s16 * 32 + q * 4;
                a[mt][0] = *(const uint32_t*)(p);
                a[mt][1] = *(const uint32_t*)(p + 640);
                a[mt][2] = *(const uint32_t*)(p + 16);
                a[mt][3] = *(const uint32_t*)(p + 656);
            }
#pragma unroll
            for (int nt = 0; nt < 8; nt++) {
                const char* pb = Bb + (wn * 64 + nt * 8 + r) * 80 + s16 * 32 + q * 4;
                uint32_t b0 = *(const uint32_t*)(pb);
                uint32_t b1 = *(const uint32_t*)(pb + 16);
                mma_fp16(acc[0][nt], a[0], b0, b1);
                mma_fp16(acc[1][nt], a[1], b0, b1);
            }
        }
    }

    // epilogue: + bias (u1 folded into Wu2)
#pragma unroll
    for (int mt = 0; mt < 2; mt++) {
#pragma unroll
        for (int nt = 0; nt < 8; nt++) {
            const int rw = m0 + wm * 32 + mt * 16 + r;
            const int cl = wn * 64 + nt * 8 + 2 * q;
            const int col = n0 + cl;
            float2 p0, p1;
            p0.x = acc[mt][nt][0] + bs[cl];
            p0.y = acc[mt][nt][1] + bs[cl + 1];
            p1.x = acc[mt][nt][2] + bs[cl];
            p1.y = acc[mt][nt][3] + bs[cl + 1];
            *reinterpret_cast<float2*>(out + (size_t)rw * DOUT + col) = p0;
            *reinterpret_cast<float2*>(out + (size_t)(rw + 8) * DOUT + col) = p1;
        }
    }
}

extern "C" void kernel_launch(void* const* d_in, const int* in_sizes, int n_in,
                              void* d_out, int out_size) {
    const float* x    = (const float*)d_in[0];
    const float* V    = (const float*)d_in[1];
    const float* U    = (const float*)d_in[2];
    const float* v1   = (const float*)d_in[3];
    const float* v2   = (const float*)d_in[4];
    const float* u1   = (const float*)d_in[5];
    const float* u2   = (const float*)d_in[6];
    const float* VR   = (const float*)d_in[7];
    const float* UR   = (const float*)d_in[8];
    const float* v1R  = (const float*)d_in[9];
    const float* v2R  = (const float*)d_in[10];
    const float* u1R  = (const float*)d_in[11];
    const float* u2R  = (const float*)d_in[12];
    const float* bias = (const float*)d_in[13];
    float* out = (float*)d_out;

    static bool attr_set = false;
    if (!attr_set) {
        cudaFuncSetAttribute(k1_kernel, cudaFuncAttributeMaxDynamicSharedMemorySize, GSMEM);
        cudaFuncSetAttribute(k2_kernel, cudaFuncAttributeMaxDynamicSharedMemorySize, GSMEM);
        attr_set = true;
    }

    kc_kernel<<<(NTOK * (size_t)DIN) / (256 * 8), 256>>>(x);
    kw_kernel<<<8192, 256>>>(V, VR, U, UR, v2, v2R, u1, u1R);
    k1_kernel<<<dim3(NTOK / 128, 4), 256, GSMEM>>>(v1, u2, v1R, u2R);
    k2_kernel<<<dim3(NTOK / 128, DOUT / 128), 256, GSMEM>>>(bias, out);
}

// round 9
// speedup vs baseline: 3.9527x; 1.2011x over previous
#include <cuda_runtime.h>
#include <cuda_fp16.h>
#include <cstdint>
#include <cstddef>

#define NTOK 8192
#define DIN  4096
#define DOUT 4096

// -------- device scratch --------
__device__ __half g_xh[(size_t)NTOK * DIN];    // fp16(x)
__device__ __half g_Wv2[(size_t)512 * DIN];    // [s 512][k 4096]  fp16(sign(V_b)*v2_b[k])
__device__ __half g_Wu2[(size_t)DOUT * 512];   // [n 4096][k 512]  fp16(sign(U_b)*u1_b[n])
__device__ __half g_h[(size_t)NTOK * 512];     // fp16 intermediate (v1*u2 applied)

// -------- helpers --------
__device__ __forceinline__ uint32_t smem_u32(const void* p) {
    uint32_t a;
    asm("{ .reg .u64 t; cvta.to.shared.u64 t, %1; cvt.u32.u64 %0, t; }" : "=r"(a) : "l"(p));
    return a;
}
__device__ __forceinline__ void cpa16(uint32_t dst, const void* src) {
    asm volatile("cp.async.cg.shared.global [%0], [%1], 16;" :: "r"(dst), "l"(src) : "memory");
}
#define CP_COMMIT() asm volatile("cp.async.commit_group;" ::: "memory")
#define CP_WAIT2()  asm volatile("cp.async.wait_group 2;" ::: "memory")

__device__ __forceinline__ void mma_fp16(float* c, const uint32_t* a, uint32_t b0, uint32_t b1) {
    asm volatile(
        "mma.sync.aligned.m16n8k16.row.col.f32.f16.f16.f32 "
        "{%0,%1,%2,%3}, {%4,%5,%6,%7}, {%8,%9}, {%0,%1,%2,%3};"
        : "+f"(c[0]), "+f"(c[1]), "+f"(c[2]), "+f"(c[3])
        : "r"(a[0]), "r"(a[1]), "r"(a[2]), "r"(a[3]), "r"(b0), "r"(b1));
}
#define LDSM_X4(r0, r1, r2, r3, addr) \
    asm volatile("ldmatrix.sync.aligned.m8n8.x4.shared.b16 {%0,%1,%2,%3}, [%4];" \
                 : "=r"(r0), "=r"(r1), "=r"(r2), "=r"(r3) : "r"(addr))

// -------- smem geometry --------
// A tile: 128 rows x 32 fp16 (64B data), row stride 80B -> 10240B
// B tile: 128 rows x 32 fp16 (64B data), row stride 80B -> 10240B
// stage = 20480B, 4 stages = 81920B -> 2 CTAs/SM
#define BOFF 10240
#define STG  20480
#define GSMEM (4 * STG + 1024)

// -------- kc: x -> fp16 --------
__global__ void kc_kernel(const float* __restrict__ x) {
    size_t i = ((size_t)blockIdx.x * blockDim.x + threadIdx.x) * 8;
    if (i >= (size_t)NTOK * DIN) return;
    float4 a = *reinterpret_cast<const float4*>(x + i);
    float4 b = *reinterpret_cast<const float4*>(x + i + 4);
    __half2 h0 = __floats2half2_rn(a.x, a.y);
    __half2 h1 = __floats2half2_rn(a.z, a.w);
    __half2 h2 = __floats2half2_rn(b.x, b.y);
    __half2 h3 = __floats2half2_rn(b.z, b.w);
    uint2 o, o2;
    o.x  = *reinterpret_cast<uint32_t*>(&h0);
    o.y  = *reinterpret_cast<uint32_t*>(&h1);
    o2.x = *reinterpret_cast<uint32_t*>(&h2);
    o2.y = *reinterpret_cast<uint32_t*>(&h3);
    *reinterpret_cast<uint2*>(g_xh + i) = o;
    *reinterpret_cast<uint2*>(g_xh + i + 4) = o2;
}

// -------- kw: fold scales into sign weights (fp16) --------
__global__ void kw_kernel(const float* __restrict__ V,  const float* __restrict__ VR,
                          const float* __restrict__ U,  const float* __restrict__ UR,
                          const float* __restrict__ v2, const float* __restrict__ v2R,
                          const float* __restrict__ u1, const float* __restrict__ u1R) {
    int i = blockIdx.x * blockDim.x + threadIdx.x;
    if (i >= 512 * DIN) return;
    {
        int s = i >> 12, k = i & (DIN - 1);
        float w  = (s < 256) ? V[(size_t)s * DIN + k] : VR[(size_t)(s - 256) * DIN + k];
        float sv = (s < 256) ? v2[k] : v2R[k];
        float sg = (w > 0.f) ? 1.f : ((w < 0.f) ? -1.f : 0.f);
        g_Wv2[i] = __float2half(sg * sv);
    }
    {
        int n = i >> 9, kk = i & 511;
        float w  = (kk < 256) ? U[(size_t)n * 256 + kk] : UR[(size_t)n * 256 + (kk - 256)];
        float su = (kk < 256) ? u1[n] : u1R[n];
        float sg = (w > 0.f) ? 1.f : ((w < 0.f) ? -1.f : 0.f);
        g_Wu2[i] = __float2half(sg * su);
    }
}

// lane-invariant ldmatrix offsets
// A x4 (m16k16): lanes 0-15 -> rows R0+0..15 (col 0..7), lanes 16-31 -> same rows col bytes +16
// B x4 (two n8 x k16): lanes 0-7 rows N0+0..7 @+0; 8-15 same rows @+16; 16-23 rows N0+8..15 @+0; 24-31 @+16
__device__ __forceinline__ uint32_t a_lane_off(int wm, int lane) {
    return (uint32_t)((wm * 32 + (lane & 15)) * 80 + (lane >> 4) * 16);
}
__device__ __forceinline__ uint32_t b_lane_off(int wn, int lane) {
    return (uint32_t)((wn * 64 + ((lane >> 4) << 3) + (lane & 7)) * 80 + (((lane >> 3) & 1) << 4));
}

// -------- k1: h[m, 512] = fp16( (x @ Wv2^T) * (v1*u2) ) --------
// grid (64, 4): y = branch*2 + nhalf. CTA tile 128x128, ktile 32, 128 iters.
__global__ void __launch_bounds__(256, 2) k1_kernel(
    const float* __restrict__ v1a, const float* __restrict__ u2a,
    const float* __restrict__ v1b, const float* __restrict__ u2b)
{
    extern __shared__ char sm[];
    const uint32_t smb = smem_u32(sm);
    const int tid = threadIdx.x, warp = tid >> 5, lane = tid & 31;
    const int r = lane >> 2, q = lane & 3;
    const int wm = warp >> 1, wn = warp & 1;
    const int m0 = blockIdx.x * 128;
    const int by = blockIdx.y;
    const int br = by >> 1, nb = (by & 1) * 128;

    float* sc = reinterpret_cast<float*>(sm + 4 * STG);
    if (tid < 128) {
        const float* v1 = br ? v1b : v1a;
        const float* u2 = br ? u2b : u2a;
        sc[tid] = v1[nb + tid] * u2[nb + tid];
    }
    const int row = tid >> 1, half = tid & 1;
    const uint32_t aoff = a_lane_off(wm, lane);
    const uint32_t boff = b_lane_off(wn, lane) + BOFF;

    auto issue = [&](int j) {
        if (j < 128) {
            const int s4 = j & 3, k0 = j * 32;
            uint32_t xd = smb + s4 * STG + row * 80 + half * 32;
            const __half* xs = g_xh + (size_t)(m0 + row) * DIN + k0 + half * 16;
            cpa16(xd, xs);
            cpa16(xd + 16, xs + 8);
            uint32_t bd = smb + s4 * STG + BOFF + row * 80 + half * 32;
            const __half* bsrc = g_Wv2 + (size_t)(br * 256 + nb + row) * DIN + k0 + half * 16;
            cpa16(bd, bsrc);
            cpa16(bd + 16, bsrc + 8);
        }
        CP_COMMIT();
    };
    issue(0); issue(1); issue(2);

    float acc[2][8][4];
#pragma unroll
    for (int a = 0; a < 2; a++)
#pragma unroll
        for (int b = 0; b < 8; b++)
#pragma unroll
            for (int c = 0; c < 4; c++) acc[a][b][c] = 0.f;

    for (int it = 0; it < 128; ++it) {
        CP_WAIT2();
        __syncthreads();
        issue(it + 3);
        const uint32_t stg = smb + (it & 3) * STG;
#pragma unroll
        for (int s16 = 0; s16 < 2; s16++) {
            uint32_t a[2][4];
            LDSM_X4(a[0][0], a[0][1], a[0][2], a[0][3], stg + aoff + s16 * 32);
            LDSM_X4(a[1][0], a[1][1], a[1][2], a[1][3], stg + aoff + 16 * 80 + s16 * 32);
#pragma unroll
            for (int ntp = 0; ntp < 4; ntp++) {
                uint32_t b[4];
                LDSM_X4(b[0], b[1], b[2], b[3], stg + boff + ntp * (16 * 80) + s16 * 32);
                mma_fp16(acc[0][2 * ntp],     a[0], b[0], b[1]);
                mma_fp16(acc[1][2 * ntp],     a[1], b[0], b[1]);
                mma_fp16(acc[0][2 * ntp + 1], a[0], b[2], b[3]);
                mma_fp16(acc[1][2 * ntp + 1], a[1], b[2], b[3]);
            }
        }
    }

    // epilogue: scale by (v1*u2), convert fp16, store h
#pragma unroll
    for (int mt = 0; mt < 2; mt++) {
#pragma unroll
        for (int nt = 0; nt < 8; nt++) {
            const int rw = m0 + wm * 32 + mt * 16 + r;
            const int cl = wn * 64 + nt * 8 + 2 * q;
            const int col = br * 256 + nb + cl;
            const float s0 = sc[cl], s1 = sc[cl + 1];
            __half2 p0 = __floats2half2_rn(acc[mt][nt][0] * s0, acc[mt][nt][1] * s1);
            __half2 p1 = __floats2half2_rn(acc[mt][nt][2] * s0, acc[mt][nt][3] * s1);
            *reinterpret_cast<uint32_t*>(g_h + (size_t)rw * 512 + col) =
                *reinterpret_cast<uint32_t*>(&p0);
            *reinterpret_cast<uint32_t*>(g_h + (size_t)(rw + 8) * 512 + col) =
                *reinterpret_cast<uint32_t*>(&p1);
        }
    }
}

// -------- k2: y[m, n] = h @ Wu2^T + bias --------
// grid (64, 32). CTA tile 128x128, K=512, ktile 32, 16 iters.
__global__ void __launch_bounds__(256, 2) k2_kernel(
    const float* __restrict__ bias, float* __restrict__ out)
{
    extern __shared__ char sm[];
    const uint32_t smb = smem_u32(sm);
    const int tid = threadIdx.x, warp = tid >> 5, lane = tid & 31;
    const int r = lane >> 2, q = lane & 3;
    const int wm = warp >> 1, wn = warp & 1;
    const int m0 = blockIdx.x * 128;
    const int n0 = blockIdx.y * 128;

    float* bs = reinterpret_cast<float*>(sm + 4 * STG);
    if (tid < 128) bs[tid] = bias[n0 + tid];
    const int row = tid >> 1, half = tid & 1;
    const uint32_t aoff = a_lane_off(wm, lane);
    const uint32_t boff = b_lane_off(wn, lane) + BOFF;

    auto issue = [&](int j) {
        if (j < 16) {
            const int s4 = j & 3, k0 = j * 32;
            uint32_t xd = smb + s4 * STG + row * 80 + half * 32;
            const __half* xs = g_h + (size_t)(m0 + row) * 512 + k0 + half * 16;
            cpa16(xd, xs);
            cpa16(xd + 16, xs + 8);
            uint32_t bd = smb + s4 * STG + BOFF + row * 80 + half * 32;
            const __half* bsrc = g_Wu2 + (size_t)(n0 + row) * 512 + k0 + half * 16;
            cpa16(bd, bsrc);
            cpa16(bd + 16, bsrc + 8);
        }
        CP_COMMIT();
    };
    issue(0); issue(1); issue(2);

    float acc[2][8][4];
#pragma unroll
    for (int a = 0; a < 2; a++)
#pragma unroll
        for (int b = 0; b < 8; b++)
#pragma unroll
            for (int c = 0; c < 4; c++) acc[a][b][c] = 0.f;

    for (int it = 0; it < 16; ++it) {
        CP_WAIT2();
        __syncthreads();
        issue(it + 3);
        const uint32_t stg = smb + (it & 3) * STG;
#pragma unroll
        for (int s16 = 0; s16 < 2; s16++) {
            uint32_t a[2][4];
            LDSM_X4(a[0][0], a[0][1], a[0][2], a[0][3], stg + aoff + s16 * 32);
            LDSM_X4(a[1][0], a[1][1], a[1][2], a[1][3], stg + aoff + 16 * 80 + s16 * 32);
#pragma unroll
            for (int ntp = 0; ntp < 4; ntp++) {
                uint32_t b[4];
                LDSM_X4(b[0], b[1], b[2], b[3], stg + boff + ntp * (16 * 80) + s16 * 32);
                mma_fp16(acc[0][2 * ntp],     a[0], b[0], b[1]);
                mma_fp16(acc[1][2 * ntp],     a[1], b[0], b[1]);
                mma_fp16(acc[0][2 * ntp + 1], a[0], b[2], b[3]);
                mma_fp16(acc[1][2 * ntp + 1], a[1], b[2], b[3]);
            }
        }
    }

    // epilogue: + bias (u1 folded into Wu2)
#pragma unroll
    for (int mt = 0; mt < 2; mt++) {
#pragma unroll
        for (int nt = 0; nt < 8; nt++) {
            const int rw = m0 + wm * 32 + mt * 16 + r;
            const int cl = wn * 64 + nt * 8 + 2 * q;
            const int col = n0 + cl;
            float2 p0, p1;
            p0.x = acc[mt][nt][0] + bs[cl];
            p0.y = acc[mt][nt][1] + bs[cl + 1];
            p1.x = acc[mt][nt][2] + bs[cl];
            p1.y = acc[mt][nt][3] + bs[cl + 1];
            *reinterpret_cast<float2*>(out + (size_t)rw * DOUT + col) = p0;
            *reinterpret_cast<float2*>(out + (size_t)(rw + 8) * DOUT + col) = p1;
        }
    }
}

extern "C" void kernel_launch(void* const* d_in, const int* in_sizes, int n_in,
                              void* d_out, int out_size) {
    const float* x    = (const float*)d_in[0];
    const float* V    = (const float*)d_in[1];
    const float* U    = (const float*)d_in[2];
    const float* v1   = (const float*)d_in[3];
    const float* v2   = (const float*)d_in[4];
    const float* u1   = (const float*)d_in[5];
    const float* u2   = (const float*)d_in[6];
    const float* VR   = (const float*)d_in[7];
    const float* UR   = (const float*)d_in[8];
    const float* v1R  = (const float*)d_in[9];
    const float* v2R  = (const float*)d_in[10];
    const float* u1R  = (const float*)d_in[11];
    const float* u2R  = (const float*)d_in[12];
    const float* bias = (const float*)d_in[13];
    float* out = (float*)d_out;

    static bool attr_set = false;
    if (!attr_set) {
        cudaFuncSetAttribute(k1_kernel, cudaFuncAttributeMaxDynamicSharedMemorySize, GSMEM);
        cudaFuncSetAttribute(k2_kernel, cudaFuncAttributeMaxDynamicSharedMemorySize, GSMEM);
        attr_set = true;
    }

    kc_kernel<<<(NTOK * (size_t)DIN) / (256 * 8), 256>>>(x);
    kw_kernel<<<8192, 256>>>(V, VR, U, UR, v2, v2R, u1, u1R);
    k1_kernel<<<dim3(NTOK / 128, 4), 256, GSMEM>>>(v1, u2, v1R, u2R);
    k2_kernel<<<dim3(NTOK / 128, DOUT / 128), 256, GSMEM>>>(bias, out);
}